// round 4
// baseline (speedup 1.0000x reference)
#include <cuda_runtime.h>
#include <math.h>

// Problem constants
#define BB   16
#define LL   4096
#define CC   512
#define MM   (BB*LL)          // 65536 rows
#define KK   (3*CC)           // 1536

// Scratch (device globals: no allocation allowed)
__device__ float g_xp[(size_t)MM * CC];        // conv output x_p, [row][c]  (134 MB)
__device__ float g_wt[3 * CC * CC];            // w_down transposed: [k][c_in][c_out]
__device__ float g_wpT[CC * CC];               // w_pad transposed:  [c_in][c_out]
__device__ float g_psum[128 * CC];
__device__ float g_psq [128 * CC];
__device__ float g_mean[CC];
__device__ float g_rstd[CC];

// ---------------------------------------------------------------------------
// Weight prep: g_wt[k*C*C + c*C + o] = w_down[o*C*3 + c*3 + k]
//              g_wpT[c*C + o]        = w_pad [o*C + c]
// ---------------------------------------------------------------------------
__global__ void prep_weights(const float* __restrict__ wd, const float* __restrict__ wp) {
    int t = blockIdx.x * blockDim.x + threadIdx.x;
    const int total1 = 3 * CC * CC;
    if (t < total1) {
        int o = t & (CC - 1);
        int c = (t >> 9) & (CC - 1);
        int k = t >> 18;
        g_wt[t] = wd[o * (CC * 3) + c * 3 + k];
    } else {
        int t2 = t - total1;
        if (t2 < CC * CC) {
            int o = t2 & (CC - 1);
            int c = t2 >> 9;
            g_wpT[t2] = wp[o * CC + c];
        }
    }
}

// ---------------------------------------------------------------------------
// Conv as GEMM: x_p[row, o] = b_down[o] + sum_{k3,c} x[b, l+2*k3, c] * Wt[k3][c][o]
// Tile: BM=128 rows, BN=128 cols, BK=16.  256 threads, 8x8 register tile each.
// Rows l >= 4092 (per batch) read zero-padded taps; fixed up by fixup_kernel.
// ---------------------------------------------------------------------------
__global__ __launch_bounds__(256) void conv_gemm(const float* __restrict__ x,
                                                 const float* __restrict__ b_down) {
    __shared__ float As[16][128];   // [k][row]
    __shared__ float Bs[16][128];   // [k][o]

    const int tid  = threadIdx.x;
    const int row0 = blockIdx.y * 128;
    const int col0 = blockIdx.x * 128;
    const int ty = tid >> 4;        // 0..15
    const int tx = tid & 15;        // 0..15

    float acc[8][8] = {};

    for (int k0 = 0; k0 < KK; k0 += 16) {
        const int k3 = k0 >> 9;         // tap 0..2 (chunk never straddles taps)
        const int c0 = k0 & (CC - 1);

        // ---- load A tile: 128 rows x 16 k, 2 float4 per thread ----
        #pragma unroll
        for (int it = 0; it < 2; ++it) {
            int idx  = tid + it * 256;          // 0..511
            int rowi = idx >> 2;                // 0..127
            int cc   = (idx & 3) << 2;          // 0,4,8,12
            int r    = row0 + rowi;
            int l    = r & (LL - 1);
            int l2   = l + 2 * k3;
            float4 v = make_float4(0.f, 0.f, 0.f, 0.f);
            if (l2 < LL) {
                v = *reinterpret_cast<const float4*>(
                        x + (size_t)((r - l) + l2) * CC + c0 + cc);
            }
            As[cc + 0][rowi] = v.x;
            As[cc + 1][rowi] = v.y;
            As[cc + 2][rowi] = v.z;
            As[cc + 3][rowi] = v.w;
        }
        // ---- load B tile: 16 k x 128 o ----
        #pragma unroll
        for (int it = 0; it < 2; ++it) {
            int idx  = tid + it * 256;          // 0..511
            int krow = idx >> 5;                // 0..15
            int oo   = (idx & 31) << 2;         // 0..124
            *reinterpret_cast<float4*>(&Bs[krow][oo]) =
                *reinterpret_cast<const float4*>(g_wt + (size_t)(k0 + krow) * CC + col0 + oo);
        }
        __syncthreads();

        #pragma unroll
        for (int kk = 0; kk < 16; ++kk) {
            float ra[8], rb[8];
            *reinterpret_cast<float4*>(&ra[0]) = *reinterpret_cast<float4*>(&As[kk][ty * 8]);
            *reinterpret_cast<float4*>(&ra[4]) = *reinterpret_cast<float4*>(&As[kk][ty * 8 + 4]);
            *reinterpret_cast<float4*>(&rb[0]) = *reinterpret_cast<float4*>(&Bs[kk][tx * 8]);
            *reinterpret_cast<float4*>(&rb[4]) = *reinterpret_cast<float4*>(&Bs[kk][tx * 8 + 4]);
            #pragma unroll
            for (int i = 0; i < 8; ++i)
                #pragma unroll
                for (int j = 0; j < 8; ++j)
                    acc[i][j] += ra[i] * rb[j];
        }
        __syncthreads();
    }

    // epilogue: + bias, store to g_xp
    float4 bd0 = *reinterpret_cast<const float4*>(b_down + col0 + tx * 8);
    float4 bd1 = *reinterpret_cast<const float4*>(b_down + col0 + tx * 8 + 4);
    #pragma unroll
    for (int i = 0; i < 8; ++i) {
        size_t off = (size_t)(row0 + ty * 8 + i) * CC + col0 + tx * 8;
        float4 v0 = make_float4(acc[i][0] + bd0.x, acc[i][1] + bd0.y,
                                acc[i][2] + bd0.z, acc[i][3] + bd0.w);
        float4 v1 = make_float4(acc[i][4] + bd1.x, acc[i][5] + bd1.y,
                                acc[i][6] + bd1.z, acc[i][7] + bd1.w);
        *reinterpret_cast<float4*>(g_xp + off)     = v0;
        *reinterpret_cast<float4*>(g_xp + off + 4) = v1;
    }
}

// ---------------------------------------------------------------------------
// Fixup: x_p[b, :, 4092+p] = b_pad + W_pad . x[b, p, :],  p in 0..3
// One block per (b,p); 512 threads, one output channel each.
// ---------------------------------------------------------------------------
__global__ void fixup_kernel(const float* __restrict__ x, const float* __restrict__ b_pad) {
    __shared__ float xr[CC];
    const int b = blockIdx.x >> 2;
    const int p = blockIdx.x & 3;
    const int o = threadIdx.x;
    xr[o] = x[((size_t)b * LL + p) * CC + o];
    __syncthreads();
    float s = b_pad[o];
    #pragma unroll 8
    for (int c = 0; c < CC; ++c)
        s += xr[c] * g_wpT[c * CC + o];
    g_xp[((size_t)b * LL + (LL - 4) + p) * CC + o] = s;
}

// ---------------------------------------------------------------------------
// BN stats, stage 1: deterministic per-chunk partial sums (128 chunks x 512 rows)
// ---------------------------------------------------------------------------
__global__ void stats_partial() {
    const int c     = threadIdx.x;
    const int chunk = blockIdx.x;
    const float* p  = g_xp + (size_t)chunk * 512 * CC + c;
    float s = 0.f, q = 0.f;
    #pragma unroll 8
    for (int i = 0; i < 512; ++i) {
        float v = p[(size_t)i * CC];
        s += v;
        q += v * v;
    }
    g_psum[chunk * CC + c] = s;
    g_psq [chunk * CC + c] = q;
}

// Stage 2: reduce 128 partials -> mean, rstd
__global__ void stats_final() {
    const int c = threadIdx.x;
    float s = 0.f, q = 0.f;
    #pragma unroll 8
    for (int k = 0; k < 128; ++k) {
        s += g_psum[k * CC + c];
        q += g_psq [k * CC + c];
    }
    const float inv_n = 1.f / (float)MM;
    float mean = s * inv_n;
    float var  = q * inv_n - mean * mean;
    g_mean[c] = mean;
    g_rstd[c] = rsqrtf(var + 1e-5f);
}

// ---------------------------------------------------------------------------
// Fused BN + ELU + residual + MaxPool(3,2,pad=1) + final transpose.
// out[b, t, c] = max_{dl in {-1,0,1}} y(b, 2t+dl, c), y(-1) = -inf
// y(l) = elu((x_p[l]-mean)*rstd*gamma + beta) + x[b, l, c]
// One thread per (b, t, 4 channels).
// ---------------------------------------------------------------------------
__global__ __launch_bounds__(256) void pool_kernel(const float* __restrict__ x,
                                                   const float* __restrict__ gamma,
                                                   const float* __restrict__ beta,
                                                   float* __restrict__ out) {
    int idx = blockIdx.x * blockDim.x + threadIdx.x;   // total 16*2048*128
    int c  = (idx & 127) << 2;
    int t  = (idx >> 7) & 2047;
    int b  = idx >> 18;

    float4 mean = *reinterpret_cast<const float4*>(g_mean + c);
    float4 rstd = *reinterpret_cast<const float4*>(g_rstd + c);
    float4 ga   = *reinterpret_cast<const float4*>(gamma + c);
    float4 be   = *reinterpret_cast<const float4*>(beta + c);

    float4 m = make_float4(-INFINITY, -INFINITY, -INFINITY, -INFINITY);

    #pragma unroll
    for (int dl = -1; dl <= 1; ++dl) {
        int l = 2 * t + dl;
        if (l < 0) continue;                 // right edge never exceeds L-1
        size_t off = ((size_t)b * LL + l) * CC + c;
        float4 xp = *reinterpret_cast<const float4*>(g_xp + off);
        float4 xr = *reinterpret_cast<const float4*>(x + off);
        float v, y;
        v = (xp.x - mean.x) * rstd.x * ga.x + be.x; y = (v > 0.f ? v : expm1f(v)) + xr.x; m.x = fmaxf(m.x, y);
        v = (xp.y - mean.y) * rstd.y * ga.y + be.y; y = (v > 0.f ? v : expm1f(v)) + xr.y; m.y = fmaxf(m.y, y);
        v = (xp.z - mean.z) * rstd.z * ga.z + be.z; y = (v > 0.f ? v : expm1f(v)) + xr.z; m.z = fmaxf(m.z, y);
        v = (xp.w - mean.w) * rstd.w * ga.w + be.w; y = (v > 0.f ? v : expm1f(v)) + xr.w; m.w = fmaxf(m.w, y);
    }
    *reinterpret_cast<float4*>(out + ((size_t)b * 2048 + t) * CC + c) = m;
}

// ---------------------------------------------------------------------------
extern "C" void kernel_launch(void* const* d_in, const int* in_sizes, int n_in,
                              void* d_out, int out_size) {
    const float* x      = (const float*)d_in[0];
    const float* w_down = (const float*)d_in[1];
    const float* b_down = (const float*)d_in[2];
    const float* w_pad  = (const float*)d_in[3];
    const float* b_pad  = (const float*)d_in[4];
    const float* gamma  = (const float*)d_in[5];
    const float* beta   = (const float*)d_in[6];
    float* out = (float*)d_out;

    (void)in_sizes; (void)n_in; (void)out_size;

    prep_weights<<<(3 * CC * CC + CC * CC) / 256, 256>>>(w_down, w_pad);

    dim3 gemm_grid(CC / 128, MM / 128);          // (4, 512)
    conv_gemm<<<gemm_grid, 256>>>(x, b_down);

    fixup_kernel<<<BB * 4, CC>>>(x, b_pad);

    stats_partial<<<128, CC>>>();
    stats_final<<<1, CC>>>();

    pool_kernel<<<(BB * 2048 * (CC / 4)) / 256, 256>>>(x, gamma, beta, out);
}

// round 7
// speedup vs baseline: 2.2132x; 2.2132x over previous
#include <cuda_runtime.h>
#include <cuda_bf16.h>
#include <math.h>
#include <stdint.h>

#define BB 16
#define LL 4096
#define CC 512
#define MM (BB*LL)          // 65536
#define KK 1536
#define NCHUNK 24           // K chunks of 64

// ---------------- device scratch (no allocations allowed) ----------------
__device__ float          g_xp [(size_t)MM * CC];   // conv output (134 MB)
__device__ __nv_bfloat16  g_xh [(size_t)MM * CC];   // x hi (67 MB)
__device__ __nv_bfloat16  g_xl [(size_t)MM * CC];   // x lo (67 MB)
__device__ __nv_bfloat16  g_wbh[CC * KK];           // B[o][klin] hi
__device__ __nv_bfloat16  g_wbl[CC * KK];           // B[o][klin] lo
__device__ float          g_wpT[CC * CC];
__device__ float          g_psum[512 * CC];
__device__ float          g_psq [512 * CC];
__device__ float          g_mean[CC];
__device__ float          g_rstd[CC];

// ---------------- helpers ----------------
__device__ __forceinline__ uint32_t smem_u32(const void* p) {
    uint32_t a;
    asm("{ .reg .u64 t; cvta.to.shared.u64 t, %1; cvt.u32.u64 %0, t; }" : "=r"(a) : "l"(p));
    return a;
}

#define LDMX4(r, a)                                                                   \
    asm volatile("ldmatrix.sync.aligned.m8n8.x4.shared.b16 {%0,%1,%2,%3}, [%4];"      \
        : "=r"((r)[0]), "=r"((r)[1]), "=r"((r)[2]), "=r"((r)[3]) : "r"(a))

__device__ __forceinline__ void mma16816(float* d, const uint32_t* a,
                                         uint32_t b0, uint32_t b1) {
    asm volatile(
        "mma.sync.aligned.m16n8k16.row.col.f32.bf16.bf16.f32 "
        "{%0,%1,%2,%3}, {%4,%5,%6,%7}, {%8,%9}, {%0,%1,%2,%3};"
        : "+f"(d[0]), "+f"(d[1]), "+f"(d[2]), "+f"(d[3])
        : "r"(a[0]), "r"(a[1]), "r"(a[2]), "r"(a[3]), "r"(b0), "r"(b1));
}

#define CP_ASYNC(dst, src, sz)                                                        \
    asm volatile("cp.async.cg.shared.global [%0], [%1], 16, %2;"                      \
        :: "r"(dst), "l"(src), "r"(sz))
#define CP_COMMIT() asm volatile("cp.async.commit_group;" ::: "memory")
#define CP_WAIT1()  asm volatile("cp.async.wait_group 1;" ::: "memory")
#define CP_WAIT0()  asm volatile("cp.async.wait_group 0;" ::: "memory")

// ---------------- prep: weights ----------------
__global__ void prep_weights(const float* __restrict__ wd, const float* __restrict__ wp) {
    int t = blockIdx.x * blockDim.x + threadIdx.x;
    const int nwb = CC * KK;
    if (t < nwb) {
        int o = t / KK;
        int rem = t - o * KK;
        int tap = rem >> 9;
        int c = rem & 511;
        float v = wd[o * KK + c * 3 + tap];
        __nv_bfloat16 h = __float2bfloat16(v);
        g_wbh[t] = h;
        g_wbl[t] = __float2bfloat16(v - __bfloat162float(h));
    } else {
        int t2 = t - nwb;
        if (t2 < CC * CC) {
            int o = t2 & 511, c = t2 >> 9;
            g_wpT[t2] = wp[o * CC + c];
        }
    }
}

// ---------------- prep: x -> bf16 hi/lo ----------------
__global__ __launch_bounds__(256) void convert_x(const float* __restrict__ x) {
    size_t i = ((size_t)blockIdx.x * blockDim.x + threadIdx.x) * 4;
    float4 v = *reinterpret_cast<const float4*>(x + i);
    __nv_bfloat16 h0 = __float2bfloat16(v.x), h1 = __float2bfloat16(v.y);
    __nv_bfloat16 h2 = __float2bfloat16(v.z), h3 = __float2bfloat16(v.w);
    __nv_bfloat16 l0 = __float2bfloat16(v.x - __bfloat162float(h0));
    __nv_bfloat16 l1 = __float2bfloat16(v.y - __bfloat162float(h1));
    __nv_bfloat16 l2 = __float2bfloat16(v.z - __bfloat162float(h2));
    __nv_bfloat16 l3 = __float2bfloat16(v.w - __bfloat162float(h3));
    reinterpret_cast<__nv_bfloat162*>(g_xh + i)[0] = __halves2bfloat162(h0, h1);
    reinterpret_cast<__nv_bfloat162*>(g_xh + i)[1] = __halves2bfloat162(h2, h3);
    reinterpret_cast<__nv_bfloat162*>(g_xl + i)[0] = __halves2bfloat162(l0, l1);
    reinterpret_cast<__nv_bfloat162*>(g_xl + i)[1] = __halves2bfloat162(l2, l3);
}

// ---------------- bf16 mma.sync GEMM ----------------
// CTA tile 128(M) x 128(N), BK=64.  8 warps: 2(M) x 4(N), warp tile 64x32.
// Stage (64 KB): Ah(16K) Al(16K) Bh(16K) Bl(16K); 2 stages = 128 KB.
// SW128-style XOR swizzle on 128-byte rows: phys_seg = seg ^ (row & 7).
#define STAGE_BYTES 65536
#define SMEM_TOTAL_GEMM (2 * STAGE_BYTES)

__device__ __forceinline__ void load_chunk_async(uint32_t sb, int row0, int col0,
                                                 int q, int tid) {
    const int k0  = q * 64;
    const int tap = k0 >> 9;
    const int c0  = k0 & 511;
    // A: 128 rows x 64 bf16 (128B rows), hi + lo
    #pragma unroll
    for (int it = 0; it < 4; ++it) {
        int u    = tid + it * 256;          // 0..1023
        int rowi = u >> 3;
        int seg  = u & 7;
        int r  = row0 + rowi;
        int l  = r & (LL - 1);
        int l2 = l + 2 * tap;
        int valid = (l2 < LL);
        size_t src = (size_t)((r - l) + (valid ? l2 : 0)) * CC + c0 + seg * 8;
        uint32_t dst = sb + rowi * 128 + ((seg ^ (rowi & 7)) << 4);
        int sz = valid ? 16 : 0;
        CP_ASYNC(dst,         g_xh + src, sz);
        CP_ASYNC(dst + 16384, g_xl + src, sz);
    }
    // B: 128 n-rows x 64 bf16, hi + lo
    #pragma unroll
    for (int it = 0; it < 4; ++it) {
        int u    = tid + it * 256;
        int rowi = u >> 3;
        int seg  = u & 7;
        size_t src = (size_t)(col0 + rowi) * KK + k0 + seg * 8;
        uint32_t dst = sb + 32768 + rowi * 128 + ((seg ^ (rowi & 7)) << 4);
        CP_ASYNC(dst,         g_wbh + src, 16);
        CP_ASYNC(dst + 16384, g_wbl + src, 16);
    }
}

__global__ __launch_bounds__(256, 1) void conv_gemm_mma(const float* __restrict__ b_down) {
    extern __shared__ char smem[];
    const uint32_t sbase = smem_u32(smem);
    const int tid  = threadIdx.x;
    const int wid  = tid >> 5;
    const int lane = tid & 31;
    const int col0 = blockIdx.x * 128;
    const int row0 = blockIdx.y * 128;
    const int wm = wid >> 2;          // 0..1 -> 64 M-rows
    const int wn = wid & 3;           // 0..3 -> 32 N-cols

    float acc[4][4][4];
    #pragma unroll
    for (int i = 0; i < 4; ++i)
        #pragma unroll
        for (int j = 0; j < 4; ++j)
            #pragma unroll
            for (int k = 0; k < 4; ++k) acc[i][j][k] = 0.f;

    load_chunk_async(sbase,               row0, col0, 0, tid);
    CP_COMMIT();
    load_chunk_async(sbase + STAGE_BYTES, row0, col0, 1, tid);
    CP_COMMIT();

    const int rsel = lane & 15;
    const int ksg  = lane >> 4;

    for (int q = 0; q < NCHUNK; ++q) {
        if (q < NCHUNK - 1) CP_WAIT1(); else CP_WAIT0();
        __syncthreads();
        const uint32_t sb = sbase + (q & 1) * STAGE_BYTES;

        #pragma unroll
        for (int ks = 0; ks < 4; ++ks) {
            uint32_t ah[4][4], al[4][4], bh[2][4], bl[2][4];
            const int seg = 2 * ks + ksg;
            #pragma unroll
            for (int mt = 0; mt < 4; ++mt) {
                int row = wm * 64 + mt * 16 + rsel;
                uint32_t a = sb + row * 128 + ((seg ^ (row & 7)) << 4);
                LDMX4(ah[mt], a);
                LDMX4(al[mt], a + 16384);
            }
            #pragma unroll
            for (int bt = 0; bt < 2; ++bt) {
                int row = wn * 32 + bt * 16 + rsel;
                uint32_t a = sb + 32768 + row * 128 + ((seg ^ (row & 7)) << 4);
                LDMX4(bh[bt], a);
                LDMX4(bl[bt], a + 16384);
            }
            #pragma unroll
            for (int mt = 0; mt < 4; ++mt)
                #pragma unroll
                for (int nt = 0; nt < 4; ++nt) {
                    const int bt = nt >> 1, p = nt & 1;
                    mma16816(acc[mt][nt], ah[mt], bh[bt][p], bh[bt][2 + p]);
                    mma16816(acc[mt][nt], ah[mt], bl[bt][p], bl[bt][2 + p]);
                    mma16816(acc[mt][nt], al[mt], bh[bt][p], bh[bt][2 + p]);
                }
        }
        __syncthreads();
        if (q + 2 < NCHUNK) {
            load_chunk_async(sbase + (q & 1) * STAGE_BYTES, row0, col0, q + 2, tid);
            CP_COMMIT();
        }
    }

    // epilogue: + bias, store fp32 to g_xp
    const int lrow = lane >> 2;
    const int lcol = (lane & 3) * 2;
    #pragma unroll
    for (int mt = 0; mt < 4; ++mt) {
        const int r0 = row0 + wm * 64 + mt * 16 + lrow;
        #pragma unroll
        for (int nt = 0; nt < 4; ++nt) {
            const int col = col0 + wn * 32 + nt * 8 + lcol;
            float bv0 = b_down[col], bv1 = b_down[col + 1];
            float2 v0 = make_float2(acc[mt][nt][0] + bv0, acc[mt][nt][1] + bv1);
            float2 v1 = make_float2(acc[mt][nt][2] + bv0, acc[mt][nt][3] + bv1);
            *reinterpret_cast<float2*>(g_xp + (size_t)r0 * CC + col)       = v0;
            *reinterpret_cast<float2*>(g_xp + (size_t)(r0 + 8) * CC + col) = v1;
        }
    }
}

// ---------------- fixup (fp32, exact): rows L-4..L-1 ----------------
__global__ void fixup_kernel(const float* __restrict__ x, const float* __restrict__ b_pad) {
    __shared__ float xr[CC];
    const int b = blockIdx.x >> 2;
    const int p = blockIdx.x & 3;
    const int o = threadIdx.x;
    xr[o] = x[((size_t)b * LL + p) * CC + o];
    __syncthreads();
    float s = b_pad[o];
    #pragma unroll 8
    for (int c = 0; c < CC; ++c)
        s += xr[c] * g_wpT[c * CC + o];
    g_xp[((size_t)b * LL + (LL - 4) + p) * CC + o] = s;
}

// ---------------- BN stats ----------------
__global__ void stats_partial() {
    const int c = threadIdx.x;
    const int chunk = blockIdx.x;                 // 512 chunks x 128 rows
    const float* p = g_xp + (size_t)chunk * 128 * CC + c;
    float s = 0.f, q = 0.f;
    #pragma unroll 8
    for (int i = 0; i < 128; ++i) {
        float v = p[(size_t)i * CC];
        s += v;
        q += v * v;
    }
    g_psum[chunk * CC + c] = s;
    g_psq [chunk * CC + c] = q;
}
__global__ void stats_final() {
    const int c = threadIdx.x;
    float s = 0.f, q = 0.f;
    #pragma unroll 8
    for (int k = 0; k < 512; ++k) {
        s += g_psum[k * CC + c];
        q += g_psq [k * CC + c];
    }
    const float inv_n = 1.f / (float)MM;
    float mean = s * inv_n;
    float var  = q * inv_n - mean * mean;
    g_mean[c] = mean;
    g_rstd[c] = rsqrtf(var + 1e-5f);
}

// ---------------- fused BN+ELU+residual+maxpool ----------------
__global__ __launch_bounds__(256) void pool_kernel(const float* __restrict__ x,
                                                   const float* __restrict__ gamma,
                                                   const float* __restrict__ beta,
                                                   float* __restrict__ out) {
    int idx = blockIdx.x * blockDim.x + threadIdx.x;
    int c = (idx & 127) << 2;
    int t = (idx >> 7) & 2047;
    int b = idx >> 18;

    float4 mean = *reinterpret_cast<const float4*>(g_mean + c);
    float4 rstd = *reinterpret_cast<const float4*>(g_rstd + c);
    float4 ga   = *reinterpret_cast<const float4*>(gamma + c);
    float4 be   = *reinterpret_cast<const float4*>(beta + c);

    float4 m = make_float4(-INFINITY, -INFINITY, -INFINITY, -INFINITY);
    #pragma unroll
    for (int dl = -1; dl <= 1; ++dl) {
        int l = 2 * t + dl;
        if (l < 0) continue;
        size_t off = ((size_t)b * LL + l) * CC + c;
        float4 xp = *reinterpret_cast<const float4*>(g_xp + off);
        float4 xr = *reinterpret_cast<const float4*>(x + off);
        float v, y;
        v = (xp.x - mean.x) * rstd.x * ga.x + be.x; y = (v > 0.f ? v : expm1f(v)) + xr.x; m.x = fmaxf(m.x, y);
        v = (xp.y - mean.y) * rstd.y * ga.y + be.y; y = (v > 0.f ? v : expm1f(v)) + xr.y; m.y = fmaxf(m.y, y);
        v = (xp.z - mean.z) * rstd.z * ga.z + be.z; y = (v > 0.f ? v : expm1f(v)) + xr.z; m.z = fmaxf(m.z, y);
        v = (xp.w - mean.w) * rstd.w * ga.w + be.w; y = (v > 0.f ? v : expm1f(v)) + xr.w; m.w = fmaxf(m.w, y);
    }
    *reinterpret_cast<float4*>(out + ((size_t)b * 2048 + t) * CC + c) = m;
}

// ---------------------------------------------------------------------------
extern "C" void kernel_launch(void* const* d_in, const int* in_sizes, int n_in,
                              void* d_out, int out_size) {
    const float* x      = (const float*)d_in[0];
    const float* w_down = (const float*)d_in[1];
    const float* b_down = (const float*)d_in[2];
    const float* w_pad  = (const float*)d_in[3];
    const float* b_pad  = (const float*)d_in[4];
    const float* gamma  = (const float*)d_in[5];
    const float* beta   = (const float*)d_in[6];
    float* out = (float*)d_out;
    (void)in_sizes; (void)n_in; (void)out_size;

    cudaFuncSetAttribute(conv_gemm_mma, cudaFuncAttributeMaxDynamicSharedMemorySize,
                         SMEM_TOTAL_GEMM);

    prep_weights<<<(CC * KK + CC * CC) / 256, 256>>>(w_down, w_pad);
    convert_x<<<(size_t)MM * CC / 4 / 256, 256>>>(x);

    dim3 grid(4, 512);   // (N blocks, M blocks)
    conv_gemm_mma<<<grid, 256, SMEM_TOTAL_GEMM>>>(b_down);

    fixup_kernel<<<BB * 4, CC>>>(x, b_pad);
    stats_partial<<<512, CC>>>();
    stats_final<<<1, CC>>>();
    pool_kernel<<<(BB * 2048 * (CC / 4)) / 256, 256>>>(x, gamma, beta, out);
}

// round 8
// speedup vs baseline: 2.8957x; 1.3084x over previous
#include <cuda_runtime.h>
#include <cuda_bf16.h>
#include <math.h>
#include <stdint.h>

#define BB 16
#define LL 4096
#define CC 512
#define MM (BB*LL)          // 65536
#define KK 1536
#define NCHUNK 24           // K chunks of 64

// ---------------- device scratch ----------------
__device__ float g_xp [(size_t)MM * CC];   // conv output (134 MB)
__device__ float g_wt [CC * KK];           // W[o][klin], tf32-rounded (3 MB)
__device__ float g_wpT[CC * CC];
__device__ float g_psum[512 * CC];
__device__ float g_psq [512 * CC];
__device__ float g_mean[CC];
__device__ float g_rstd[CC];

// ---------------- helpers ----------------
__device__ __forceinline__ uint32_t smem_u32(const void* p) {
    uint32_t a;
    asm("{ .reg .u64 t; cvta.to.shared.u64 t, %1; cvt.u32.u64 %0, t; }" : "=r"(a) : "l"(p));
    return a;
}
__device__ __forceinline__ uint32_t f2tf32(float v) {
    uint32_t r;
    asm("cvt.rna.tf32.f32 %0, %1;" : "=r"(r) : "f"(v));
    return r;
}
__device__ __forceinline__ uint32_t ldsu(uint32_t a) {
    uint32_t v;
    asm volatile("ld.shared.b32 %0, [%1];" : "=r"(v) : "r"(a));
    return v;
}
__device__ __forceinline__ void mma_tf32(float* d, const uint32_t* a,
                                         uint32_t b0, uint32_t b1) {
    asm volatile(
        "mma.sync.aligned.m16n8k8.row.col.f32.tf32.tf32.f32 "
        "{%0,%1,%2,%3}, {%4,%5,%6,%7}, {%8,%9}, {%0,%1,%2,%3};"
        : "+f"(d[0]), "+f"(d[1]), "+f"(d[2]), "+f"(d[3])
        : "r"(a[0]), "r"(a[1]), "r"(a[2]), "r"(a[3]), "r"(b0), "r"(b1));
}
#define CP_ASYNC(dst, src, sz)                                                        \
    asm volatile("cp.async.cg.shared.global [%0], [%1], 16, %2;"                      \
        :: "r"(dst), "l"(src), "r"(sz))
#define CP_COMMIT() asm volatile("cp.async.commit_group;" ::: "memory")
#define CP_WAIT1()  asm volatile("cp.async.wait_group 1;" ::: "memory")

// ---------------- prep ----------------
__global__ void prep_w(const float* __restrict__ wd) {
    int t = blockIdx.x * blockDim.x + threadIdx.x;   // CC*KK
    int o = t / KK;
    int rem = t - o * KK;
    int tap = rem >> 9;
    int c = rem & 511;
    uint32_t r = f2tf32(wd[o * KK + c * 3 + tap]);
    g_wt[t] = __uint_as_float(r);
}
__global__ void prep_wp(const float* __restrict__ wp) {
    int t = blockIdx.x * blockDim.x + threadIdx.x;   // CC*CC
    int o = t & 511, c = t >> 9;
    g_wpT[t] = wp[o * CC + c];
}
__global__ void dummy_k() {}   // pads launch index so GEMM is launch #4 for ncu

// ---------------- tf32 mma GEMM ----------------
// CTA 128M x 128N, BK=64, 8 warps (2 wm x 4 wn), warp tile 64x32.
// Stage 64 KB: A 128x64 f32 (256B rows, 16B-seg XOR swizzle seg^(r&15)), B same.
// 3 stages (192 KB) + 4 KB stats buffers.
#define STAGE_BYTES 65536
#define SMEM_STATS  (3 * STAGE_BYTES)
#define SMEM_TOTAL_GEMM (SMEM_STATS + 4096)

__device__ __forceinline__ void load_chunk(uint32_t sA, int row0, int col0,
                                           int q, int tid, const float* __restrict__ x) {
    const int k0  = q * 64;
    const int tap = k0 >> 9;
    const int c0  = k0 & 511;
    #pragma unroll
    for (int it = 0; it < 8; ++it) {               // A: 128 rows x 16 segs
        int u = tid + it * 256;
        int r = u >> 4, seg = u & 15;
        int R = row0 + r;
        int l = R & (LL - 1);
        int l2 = l + 2 * tap;
        int valid = (l2 < LL);
        const float* src = x + (size_t)((R - l) + (valid ? l2 : 0)) * CC + c0 + seg * 4;
        uint32_t dst = sA + r * 256 + ((seg ^ (r & 15)) << 4);
        CP_ASYNC(dst, src, valid ? 16 : 0);
    }
    #pragma unroll
    for (int it = 0; it < 8; ++it) {               // B: 128 n-rows x 16 segs
        int u = tid + it * 256;
        int n = u >> 4, seg = u & 15;
        const float* src = g_wt + (size_t)(col0 + n) * KK + k0 + seg * 4;
        uint32_t dst = sA + 32768 + n * 256 + ((seg ^ (n & 15)) << 4);
        CP_ASYNC(dst, src, 16);
    }
}

__global__ __launch_bounds__(256, 1) void conv_gemm_mma(const float* __restrict__ x,
                                                        const float* __restrict__ b_down) {
    extern __shared__ char smem[];
    const uint32_t sbase = smem_u32(smem);
    const int tid  = threadIdx.x;
    const int wid  = tid >> 5;
    const int lane = tid & 31;
    const int col0 = blockIdx.x * 128;
    const int row0 = blockIdx.y * 128;
    const int wm = wid >> 2;
    const int wn = wid & 3;
    const int g   = lane >> 2;        // 0..7
    const int tig = lane & 3;         // 0..3

    float acc[4][4][4];
    #pragma unroll
    for (int i = 0; i < 4; ++i)
        #pragma unroll
        for (int j = 0; j < 4; ++j)
            #pragma unroll
            for (int k = 0; k < 4; ++k) acc[i][j][k] = 0.f;

    load_chunk(sbase,               row0, col0, 0, tid, x); CP_COMMIT();
    load_chunk(sbase + STAGE_BYTES, row0, col0, 1, tid, x); CP_COMMIT();

    for (int q = 0; q < NCHUNK; ++q) {
        CP_WAIT1();
        __syncthreads();
        if (q + 2 < NCHUNK) {
            load_chunk(sbase + ((q + 2) % 3) * STAGE_BYTES, row0, col0, q + 2, tid, x);
            CP_COMMIT();
        }
        const uint32_t sA = sbase + (q % 3) * STAGE_BYTES;
        const uint32_t sB = sA + 32768;

        #pragma unroll
        for (int s = 0; s < 8; ++s) {
            uint32_t af[4][4], bf[4][2];
            #pragma unroll
            for (int mt = 0; mt < 4; ++mt) {
                int r1 = wm * 64 + mt * 16 + g, r2 = r1 + 8;
                uint32_t b1a = sA + r1 * 256 + tig * 4;
                uint32_t b2a = sA + r2 * 256 + tig * 4;
                int x1 = r1 & 15, x2 = r2 & 15;
                af[mt][0] = f2tf32(__uint_as_float(ldsu(b1a + (((2*s  ) ^ x1) << 4))));
                af[mt][1] = f2tf32(__uint_as_float(ldsu(b2a + (((2*s  ) ^ x2) << 4))));
                af[mt][2] = f2tf32(__uint_as_float(ldsu(b1a + (((2*s+1) ^ x1) << 4))));
                af[mt][3] = f2tf32(__uint_as_float(ldsu(b2a + (((2*s+1) ^ x2) << 4))));
            }
            #pragma unroll
            for (int nt = 0; nt < 4; ++nt) {
                int n = wn * 32 + nt * 8 + g;
                uint32_t bb = sB + n * 256 + tig * 4;
                int xn = n & 15;
                bf[nt][0] = ldsu(bb + (((2*s  ) ^ xn) << 4));
                bf[nt][1] = ldsu(bb + (((2*s+1) ^ xn) << 4));
            }
            #pragma unroll
            for (int mt = 0; mt < 4; ++mt)
                #pragma unroll
                for (int nt = 0; nt < 4; ++nt)
                    mma_tf32(acc[mt][nt], af[mt], bf[nt][0], bf[nt][1]);
        }
    }

    // ---- epilogue: bias + store + fused per-CTA BN partial stats ----
    float* bufS = reinterpret_cast<float*>(smem + SMEM_STATS);         // [2][128]
    float* bufQ = reinterpret_cast<float*>(smem + SMEM_STATS + 2048);  // [2][128]

    bool mval[4][2];
    #pragma unroll
    for (int mt = 0; mt < 4; ++mt) {
        #pragma unroll
        for (int h = 0; h < 2; ++h) {
            int l = (row0 + wm * 64 + mt * 16 + g + h * 8) & (LL - 1);
            mval[mt][h] = (l < LL - 4);     // fixup rows excluded
        }
    }

    float sum_[4][2] = {}, sq_[4][2] = {};
    #pragma unroll
    for (int nt = 0; nt < 4; ++nt) {
        const int col = col0 + wn * 32 + nt * 8 + tig * 2;
        float bv0 = __ldg(b_down + col), bv1 = __ldg(b_down + col + 1);
        #pragma unroll
        for (int mt = 0; mt < 4; ++mt) {
            const int r0 = row0 + wm * 64 + mt * 16 + g;
            float v00 = acc[mt][nt][0] + bv0, v01 = acc[mt][nt][1] + bv1;
            float v10 = acc[mt][nt][2] + bv0, v11 = acc[mt][nt][3] + bv1;
            *reinterpret_cast<float2*>(g_xp + (size_t)r0 * CC + col)       = make_float2(v00, v01);
            *reinterpret_cast<float2*>(g_xp + (size_t)(r0 + 8) * CC + col) = make_float2(v10, v11);
            if (mval[mt][0]) { sum_[nt][0] += v00; sq_[nt][0] += v00 * v00;
                               sum_[nt][1] += v01; sq_[nt][1] += v01 * v01; }
            if (mval[mt][1]) { sum_[nt][0] += v10; sq_[nt][0] += v10 * v10;
                               sum_[nt][1] += v11; sq_[nt][1] += v11 * v11; }
        }
    }
    #pragma unroll
    for (int nt = 0; nt < 4; ++nt)
        #pragma unroll
        for (int j = 0; j < 2; ++j) {
            float s = sum_[nt][j], qv = sq_[nt][j];
            #pragma unroll
            for (int off = 4; off < 32; off <<= 1) {
                s  += __shfl_xor_sync(0xffffffffu, s,  off);
                qv += __shfl_xor_sync(0xffffffffu, qv, off);
            }
            if (lane < 4) {
                int cl = wn * 32 + nt * 8 + lane * 2 + j;
                bufS[wm * 128 + cl] = s;
                bufQ[wm * 128 + cl] = qv;
            }
        }
    __syncthreads();
    if (tid < 128)
        g_psum[(size_t)blockIdx.y * CC + col0 + tid] = bufS[tid] + bufS[128 + tid];
    else if (tid < 256) {
        int c = tid - 128;
        g_psq[(size_t)blockIdx.y * CC + col0 + c] = bufQ[c] + bufQ[128 + c];
    }
}

// ---------------- fixup (fp32 exact): rows L-4..L-1 per batch ----------------
__global__ void fixup_kernel(const float* __restrict__ x, const float* __restrict__ b_pad) {
    __shared__ float xr[CC];
    const int b = blockIdx.x >> 2;
    const int p = blockIdx.x & 3;
    const int o = threadIdx.x;
    xr[o] = x[((size_t)b * LL + p) * CC + o];
    __syncthreads();
    float s = b_pad[o];
    #pragma unroll 8
    for (int c = 0; c < CC; ++c)
        s += xr[c] * g_wpT[c * CC + o];
    g_xp[((size_t)b * LL + (LL - 4) + p) * CC + o] = s;
}

// ---------------- BN stats final (GEMM partials + fixup rows) ----------------
__global__ void stats_final() {
    const int c = threadIdx.x;
    float s = 0.f, q = 0.f;
    #pragma unroll 8
    for (int k = 0; k < 512; ++k) {
        s += g_psum[k * CC + c];
        q += g_psq [k * CC + c];
    }
    #pragma unroll
    for (int b = 0; b < BB; ++b)
        #pragma unroll
        for (int p = 0; p < 4; ++p) {
            float v = g_xp[((size_t)b * LL + (LL - 4) + p) * CC + c];
            s += v;
            q += v * v;
        }
    const float inv_n = 1.f / (float)MM;
    float mean = s * inv_n;
    float var  = q * inv_n - mean * mean;
    g_mean[c] = mean;
    g_rstd[c] = rsqrtf(var + 1e-5f);
}

// ---------------- fused BN+ELU+residual+maxpool ----------------
__global__ __launch_bounds__(256) void pool_kernel(const float* __restrict__ x,
                                                   const float* __restrict__ gamma,
                                                   const float* __restrict__ beta,
                                                   float* __restrict__ out) {
    int idx = blockIdx.x * blockDim.x + threadIdx.x;
    int c = (idx & 127) << 2;
    int t = (idx >> 7) & 2047;
    int b = idx >> 18;

    float4 mean = *reinterpret_cast<const float4*>(g_mean + c);
    float4 rstd = *reinterpret_cast<const float4*>(g_rstd + c);
    float4 ga   = *reinterpret_cast<const float4*>(gamma + c);
    float4 be   = *reinterpret_cast<const float4*>(beta + c);

    float4 m = make_float4(-INFINITY, -INFINITY, -INFINITY, -INFINITY);
    #pragma unroll
    for (int dl = -1; dl <= 1; ++dl) {
        int l = 2 * t + dl;
        if (l < 0) continue;
        size_t off = ((size_t)b * LL + l) * CC + c;
        float4 xp = *reinterpret_cast<const float4*>(g_xp + off);
        float4 xr = *reinterpret_cast<const float4*>(x + off);
        float v, y;
        v = (xp.x - mean.x) * rstd.x * ga.x + be.x; y = (v > 0.f ? v : expm1f(v)) + xr.x; m.x = fmaxf(m.x, y);
        v = (xp.y - mean.y) * rstd.y * ga.y + be.y; y = (v > 0.f ? v : expm1f(v)) + xr.y; m.y = fmaxf(m.y, y);
        v = (xp.z - mean.z) * rstd.z * ga.z + be.z; y = (v > 0.f ? v : expm1f(v)) + xr.z; m.z = fmaxf(m.z, y);
        v = (xp.w - mean.w) * rstd.w * ga.w + be.w; y = (v > 0.f ? v : expm1f(v)) + xr.w; m.w = fmaxf(m.w, y);
    }
    *reinterpret_cast<float4*>(out + ((size_t)b * 2048 + t) * CC + c) = m;
}

// ---------------------------------------------------------------------------
extern "C" void kernel_launch(void* const* d_in, const int* in_sizes, int n_in,
                              void* d_out, int out_size) {
    const float* x      = (const float*)d_in[0];
    const float* w_down = (const float*)d_in[1];
    const float* b_down = (const float*)d_in[2];
    const float* w_pad  = (const float*)d_in[3];
    const float* b_pad  = (const float*)d_in[4];
    const float* gamma  = (const float*)d_in[5];
    const float* beta   = (const float*)d_in[6];
    float* out = (float*)d_out;
    (void)in_sizes; (void)n_in; (void)out_size;

    cudaFuncSetAttribute(conv_gemm_mma, cudaFuncAttributeMaxDynamicSharedMemorySize,
                         SMEM_TOTAL_GEMM);

    prep_w <<<CC * KK / 256, 256>>>(w_down);     // #1
    prep_wp<<<CC * CC / 256, 256>>>(w_pad);      // #2
    dummy_k<<<1, 32>>>();                        // #3 (ncu alignment)

    dim3 grid(4, 512);
    conv_gemm_mma<<<grid, 256, SMEM_TOTAL_GEMM>>>(x, b_down);   // #4 <- profiled

    fixup_kernel<<<BB * 4, CC>>>(x, b_pad);
    stats_final<<<1, CC>>>();
    pool_kernel<<<(BB * 2048 * (CC / 4)) / 256, 256>>>(x, gamma, beta, out);
}

// round 11
// speedup vs baseline: 3.7820x; 1.3061x over previous
#include <cuda_runtime.h>
#include <cuda_bf16.h>
#include <math.h>
#include <stdint.h>

#define BB 16
#define LL 4096
#define CC 512
#define MM (BB*LL)          // 65536
#define KK 1536
#define NCHUNK 24           // K chunks of 64

// ---------------- device scratch ----------------
__device__ float g_xp [(size_t)MM * CC];   // conv output (134 MB)
__device__ float g_wt [CC * KK];           // W[o][klin], tf32-rounded (3 MB)
__device__ float g_wpT[CC * CC];
__device__ float g_psum[512 * CC];
__device__ float g_psq [512 * CC];
__device__ float g_ps2 [64 * CC];
__device__ float g_pq2 [64 * CC];
__device__ float g_mean[CC];
__device__ float g_rstd[CC];

// ---------------- helpers ----------------
__device__ __forceinline__ uint32_t smem_u32(const void* p) {
    uint32_t a;
    asm("{ .reg .u64 t; cvta.to.shared.u64 t, %1; cvt.u32.u64 %0, t; }" : "=r"(a) : "l"(p));
    return a;
}
__device__ __forceinline__ uint32_t f2tf32(float v) {
    uint32_t r;
    asm("cvt.rna.tf32.f32 %0, %1;" : "=r"(r) : "f"(v));
    return r;
}
__device__ __forceinline__ uint32_t ldsu(uint32_t a) {
    uint32_t v;
    asm volatile("ld.shared.b32 %0, [%1];" : "=r"(v) : "r"(a));
    return v;
}
__device__ __forceinline__ void mma_tf32(float* d, const uint32_t* a,
                                         uint32_t b0, uint32_t b1) {
    asm volatile(
        "mma.sync.aligned.m16n8k8.row.col.f32.tf32.tf32.f32 "
        "{%0,%1,%2,%3}, {%4,%5,%6,%7}, {%8,%9}, {%0,%1,%2,%3};"
        : "+f"(d[0]), "+f"(d[1]), "+f"(d[2]), "+f"(d[3])
        : "r"(a[0]), "r"(a[1]), "r"(a[2]), "r"(a[3]), "r"(b0), "r"(b1));
}
#define CP_ASYNC(dst, src, sz)                                                        \
    asm volatile("cp.async.cg.shared.global [%0], [%1], 16, %2;"                      \
        :: "r"(dst), "l"(src), "r"(sz))
#define CP_COMMIT() asm volatile("cp.async.commit_group;" ::: "memory")
#define CP_WAIT1()  asm volatile("cp.async.wait_group 1;" ::: "memory")

// ---------------- prep ----------------
__global__ void prep_w(const float* __restrict__ wd) {
    int t = blockIdx.x * blockDim.x + threadIdx.x;   // CC*KK
    int o = t / KK;
    int rem = t - o * KK;
    int tap = rem >> 9;
    int c = rem & 511;
    g_wt[t] = __uint_as_float(f2tf32(wd[o * KK + c * 3 + tap]));
}
__global__ void prep_wp(const float* __restrict__ wp) {
    int t = blockIdx.x * blockDim.x + threadIdx.x;   // CC*CC
    int o = t & 511, c = t >> 9;
    g_wpT[t] = wp[o * CC + c];
}
__global__ void dummy_k() {}   // keeps GEMM at launch #4 for ncu

// ---------------- tf32 mma GEMM ----------------
// CTA 128M x 256N, BK=64.  8 warps: 2(M) x 4(N), warp tile 64x64.
// Stage 96 KB: A 128x64 f32 (256B rows, seg^(r&15) swizzle) + B 256x64 f32.
// 2 stages = 192 KB (+4 KB stats buffers).  A raw fp32 (HW tf32-truncates),
// W pre-rounded rna in prep_w.
#define STAGE_BYTES 98304
#define B_OFF       32768
#define SMEM_STATS  (2 * STAGE_BYTES)
#define SMEM_TOTAL_GEMM (SMEM_STATS + 4096)

__device__ __forceinline__ void load_chunk(uint32_t sA, int row0, int col0,
                                           int q, int tid, const float* __restrict__ x) {
    const int k0  = q * 64;
    const int tap = k0 >> 9;
    const int c0  = k0 & 511;
    #pragma unroll
    for (int it = 0; it < 8; ++it) {               // A: 128 rows x 16 segs
        int u = tid + it * 256;
        int r = u >> 4, seg = u & 15;
        int R = row0 + r;
        int l = R & (LL - 1);
        int l2 = l + 2 * tap;
        int valid = (l2 < LL);
        const float* src = x + (size_t)((R - l) + (valid ? l2 : 0)) * CC + c0 + seg * 4;
        uint32_t dst = sA + r * 256 + ((seg ^ (r & 15)) << 4);
        CP_ASYNC(dst, src, valid ? 16 : 0);
    }
    #pragma unroll
    for (int it = 0; it < 16; ++it) {              // B: 256 n-rows x 16 segs
        int u = tid + it * 256;
        int n = u >> 4, seg = u & 15;
        const float* src = g_wt + (size_t)(col0 + n) * KK + k0 + seg * 4;
        uint32_t dst = sA + B_OFF + n * 256 + ((seg ^ (n & 15)) << 4);
        CP_ASYNC(dst, src, 16);
    }
}

__global__ __launch_bounds__(256, 1) void conv_gemm_mma(const float* __restrict__ x,
                                                        const float* __restrict__ b_down) {
    extern __shared__ char smem[];
    const uint32_t sbase = smem_u32(smem);
    const int tid  = threadIdx.x;
    const int wid  = tid >> 5;
    const int lane = tid & 31;
    const int col0 = blockIdx.x * 256;
    const int row0 = blockIdx.y * 128;
    const int wm = wid >> 2;          // 0..1 -> 64 M rows
    const int wn = wid & 3;           // 0..3 -> 64 N cols
    const int g   = lane >> 2;        // 0..7
    const int tig = lane & 3;         // 0..3

    float acc[4][8][4];
    #pragma unroll
    for (int i = 0; i < 4; ++i)
        #pragma unroll
        for (int j = 0; j < 8; ++j)
            #pragma unroll
            for (int k = 0; k < 4; ++k) acc[i][j][k] = 0.f;

    load_chunk(sbase,               row0, col0, 0, tid, x); CP_COMMIT();
    load_chunk(sbase + STAGE_BYTES, row0, col0, 1, tid, x); CP_COMMIT();

    for (int q = 0; q < NCHUNK; ++q) {
        CP_WAIT1();
        __syncthreads();
        const uint32_t sA = sbase + (q & 1) * STAGE_BYTES;
        const uint32_t sB = sA + B_OFF;

        #pragma unroll
        for (int s = 0; s < 8; ++s) {
            uint32_t af[4][4];
            const uint32_t o1 = ((2*s)   ^ g)       << 4;   // r1&15 == g
            const uint32_t o2 = ((2*s)   ^ (g + 8)) << 4;   // r2&15 == g+8
            const uint32_t o3 = ((2*s+1) ^ g)       << 4;
            const uint32_t o4 = ((2*s+1) ^ (g + 8)) << 4;
            #pragma unroll
            for (int mt = 0; mt < 4; ++mt) {
                uint32_t b1a = sA + (wm * 64 + mt * 16 + g) * 256 + tig * 4;
                uint32_t b2a = b1a + 8 * 256;
                af[mt][0] = ldsu(b1a + o1);
                af[mt][1] = ldsu(b2a + o2);
                af[mt][2] = ldsu(b1a + o3);
                af[mt][3] = ldsu(b2a + o4);
            }
            #pragma unroll
            for (int nt = 0; nt < 8; ++nt) {
                int n = wn * 64 + nt * 8 + g;
                uint32_t bb = sB + n * 256 + tig * 4;
                uint32_t xn = (uint32_t)(n & 15);
                uint32_t b0 = ldsu(bb + (((2*s)   ^ xn) << 4));
                uint32_t b1 = ldsu(bb + (((2*s+1) ^ xn) << 4));
                #pragma unroll
                for (int mt = 0; mt < 4; ++mt)
                    mma_tf32(acc[mt][nt], af[mt], b0, b1);
            }
        }
        __syncthreads();
        if (q + 2 < NCHUNK) {
            load_chunk(sbase + (q & 1) * STAGE_BYTES, row0, col0, q + 2, tid, x);
            CP_COMMIT();
        }
    }

    // ---- epilogue: bias + store + fused per-CTA BN partial stats ----
    float* bufS = reinterpret_cast<float*>(smem + SMEM_STATS);         // [2][256]
    float* bufQ = reinterpret_cast<float*>(smem + SMEM_STATS + 2048);  // [2][256]

    bool mval[4][2];
    #pragma unroll
    for (int mt = 0; mt < 4; ++mt)
        #pragma unroll
        for (int h = 0; h < 2; ++h) {
            int l = (row0 + wm * 64 + mt * 16 + g + h * 8) & (LL - 1);
            mval[mt][h] = (l < LL - 4);     // fixup rows excluded from stats
        }

    #pragma unroll
    for (int nt = 0; nt < 8; ++nt) {
        const int col = col0 + wn * 64 + nt * 8 + tig * 2;
        float bv0 = __ldg(b_down + col), bv1 = __ldg(b_down + col + 1);
        float s0 = 0.f, s1 = 0.f, q0 = 0.f, q1 = 0.f;
        #pragma unroll
        for (int mt = 0; mt < 4; ++mt) {
            const int r0 = row0 + wm * 64 + mt * 16 + g;
            float v00 = acc[mt][nt][0] + bv0, v01 = acc[mt][nt][1] + bv1;
            float v10 = acc[mt][nt][2] + bv0, v11 = acc[mt][nt][3] + bv1;
            *reinterpret_cast<float2*>(g_xp + (size_t)r0 * CC + col)       = make_float2(v00, v01);
            *reinterpret_cast<float2*>(g_xp + (size_t)(r0 + 8) * CC + col) = make_float2(v10, v11);
            if (mval[mt][0]) { s0 += v00; q0 += v00 * v00; s1 += v01; q1 += v01 * v01; }
            if (mval[mt][1]) { s0 += v10; q0 += v10 * v10; s1 += v11; q1 += v11 * v11; }
        }
        #pragma unroll
        for (int off = 4; off < 32; off <<= 1) {
            s0 += __shfl_xor_sync(0xffffffffu, s0, off);
            q0 += __shfl_xor_sync(0xffffffffu, q0, off);
            s1 += __shfl_xor_sync(0xffffffffu, s1, off);
            q1 += __shfl_xor_sync(0xffffffffu, q1, off);
        }
        if (lane < 4) {
            int cl = wn * 64 + nt * 8 + lane * 2;
            bufS[wm * 256 + cl]     = s0;
            bufQ[wm * 256 + cl]     = q0;
            bufS[wm * 256 + cl + 1] = s1;
            bufQ[wm * 256 + cl + 1] = q1;
        }
    }
    __syncthreads();
    if (tid < 256) {
        g_psum[(size_t)blockIdx.y * CC + col0 + tid] = bufS[tid] + bufS[256 + tid];
        g_psq [(size_t)blockIdx.y * CC + col0 + tid] = bufQ[tid] + bufQ[256 + tid];
    }
}

// ---------------- fixup (fp32 exact): rows L-4..L-1 per batch ----------------
__global__ void fixup_kernel(const float* __restrict__ x, const float* __restrict__ b_pad) {
    __shared__ float xr[CC];
    const int b = blockIdx.x >> 2;
    const int p = blockIdx.x & 3;
    const int o = threadIdx.x;
    xr[o] = x[((size_t)b * LL + p) * CC + o];
    __syncthreads();
    float s0 = 0.f, s1 = 0.f, s2 = 0.f, s3 = 0.f;
    #pragma unroll 4
    for (int c = 0; c < CC; c += 4) {
        s0 += xr[c + 0] * g_wpT[(c + 0) * CC + o];
        s1 += xr[c + 1] * g_wpT[(c + 1) * CC + o];
        s2 += xr[c + 2] * g_wpT[(c + 2) * CC + o];
        s3 += xr[c + 3] * g_wpT[(c + 3) * CC + o];
    }
    g_xp[((size_t)b * LL + (LL - 4) + p) * CC + o] =
        b_pad[o] + ((s0 + s1) + (s2 + s3));
}

// ---------------- BN stats: 2-stage reduce of GEMM partials ----------------
__global__ void stats_mid() {
    const int c = threadIdx.x;
    const int k0 = blockIdx.x * 8;                 // 64 blocks x 8 rows
    float s = 0.f, q = 0.f;
    #pragma unroll
    for (int k = 0; k < 8; ++k) {
        s += g_psum[(k0 + k) * CC + c];
        q += g_psq [(k0 + k) * CC + c];
    }
    g_ps2[blockIdx.x * CC + c] = s;
    g_pq2[blockIdx.x * CC + c] = q;
}
__global__ void stats_final() {
    const int c = threadIdx.x;
    float s = 0.f, q = 0.f;
    #pragma unroll 8
    for (int k = 0; k < 64; ++k) {
        s += g_ps2[k * CC + c];
        q += g_pq2[k * CC + c];
    }
    #pragma unroll
    for (int b = 0; b < BB; ++b)
        #pragma unroll
        for (int p = 0; p < 4; ++p) {
            float v = g_xp[((size_t)b * LL + (LL - 4) + p) * CC + c];
            s += v;
            q += v * v;
        }
    const float inv_n = 1.f / (float)MM;
    float mean = s * inv_n;
    float var  = q * inv_n - mean * mean;
    g_mean[c] = mean;
    g_rstd[c] = rsqrtf(var + 1e-5f);
}

// ---------------- fused BN+ELU+residual+maxpool ----------------
__global__ __launch_bounds__(256) void pool_kernel(const float* __restrict__ x,
                                                   const float* __restrict__ gamma,
                                                   const float* __restrict__ beta,
                                                   float* __restrict__ out) {
    int idx = blockIdx.x * blockDim.x + threadIdx.x;
    int c = (idx & 127) << 2;
    int t = (idx >> 7) & 2047;
    int b = idx >> 18;

    float4 mean = *reinterpret_cast<const float4*>(g_mean + c);
    float4 rstd = *reinterpret_cast<const float4*>(g_rstd + c);
    float4 ga   = *reinterpret_cast<const float4*>(gamma + c);
    float4 be   = *reinterpret_cast<const float4*>(beta + c);

    float4 m = make_float4(-INFINITY, -INFINITY, -INFINITY, -INFINITY);
    #pragma unroll
    for (int dl = -1; dl <= 1; ++dl) {
        int l = 2 * t + dl;
        if (l < 0) continue;
        size_t off = ((size_t)b * LL + l) * CC + c;
        float4 xp = *reinterpret_cast<const float4*>(g_xp + off);
        float4 xr = *reinterpret_cast<const float4*>(x + off);
        float v, y;
        v = (xp.x - mean.x) * rstd.x * ga.x + be.x; y = (v > 0.f ? v : expm1f(v)) + xr.x; m.x = fmaxf(m.x, y);
        v = (xp.y - mean.y) * rstd.y * ga.y + be.y; y = (v > 0.f ? v : expm1f(v)) + xr.y; m.y = fmaxf(m.y, y);
        v = (xp.z - mean.z) * rstd.z * ga.z + be.z; y = (v > 0.f ? v : expm1f(v)) + xr.z; m.z = fmaxf(m.z, y);
        v = (xp.w - mean.w) * rstd.w * ga.w + be.w; y = (v > 0.f ? v : expm1f(v)) + xr.w; m.w = fmaxf(m.w, y);
    }
    *reinterpret_cast<float4*>(out + ((size_t)b * 2048 + t) * CC + c) = m;
}

// ---------------------------------------------------------------------------
extern "C" void kernel_launch(void* const* d_in, const int* in_sizes, int n_in,
                              void* d_out, int out_size) {
    const float* x      = (const float*)d_in[0];
    const float* w_down = (const float*)d_in[1];
    const float* b_down = (const float*)d_in[2];
    const float* w_pad  = (const float*)d_in[3];
    const float* b_pad  = (const float*)d_in[4];
    const float* gamma  = (const float*)d_in[5];
    const float* beta   = (const float*)d_in[6];
    float* out = (float*)d_out;
    (void)in_sizes; (void)n_in; (void)out_size;

    cudaFuncSetAttribute(conv_gemm_mma, cudaFuncAttributeMaxDynamicSharedMemorySize,
                         SMEM_TOTAL_GEMM);

    prep_w <<<CC * KK / 256, 256>>>(w_down);     // #1
    prep_wp<<<CC * CC / 256, 256>>>(w_pad);      // #2
    dummy_k<<<1, 32>>>();                        // #3

    dim3 grid(2, 512);                           // (N blocks of 256, M blocks of 128)
    conv_gemm_mma<<<grid, 256, SMEM_TOTAL_GEMM>>>(x, b_down);   // #4 <- profiled

    fixup_kernel<<<BB * 4, CC>>>(x, b_pad);
    stats_mid<<<64, CC>>>();
    stats_final<<<1, CC>>>();
    pool_kernel<<<(BB * 2048 * (CC / 4)) / 256, 256>>>(x, gamma, beta, out);
}